// round 16
// baseline (speedup 1.0000x reference)
#include <cuda_runtime.h>
#include <cuda_fp16.h>
#include <cstdint>

#define NCHUNK 105
#define HID    512
#define IND1   128
#define NROWS  220000
#define KD     512

// ---- big GEMM ----
#define MT     256            // rows per CTA (8 warps x m32)
#define NTILES 7              // n8 tiles per CTA (n56; 2 CTAs cover 112)
#define KSTEPS 32             // k16 steps
#define BSROW  288            // bytes per Bs row (224 used + 64 pad) -> conflict-free
#define BS_SMEM (256 * BSROW) // 73728 -> 2 CTAs/SM

// ---------------- device scratch ----------------
__device__ float  g_h1 [NCHUNK * HID];
__device__ float  g_h2 [NCHUNK * HID];
__device__ __half g_Bp [256 * 224];     // permuted fp16 B image

// ---------------- PTX helpers ----------------
__device__ __forceinline__ uint32_t smem_u32_of(const void* p) {
    uint32_t a;
    asm("{ .reg .u64 t; cvta.to.shared.u64 t, %1; cvt.u32.u64 %0, t; }" : "=r"(a) : "l"(p));
    return a;
}
__device__ __forceinline__ void mma16816(float* d, const uint32_t* a, const uint32_t* b) {
    asm volatile(
        "mma.sync.aligned.m16n8k16.row.col.f32.f16.f16.f32 "
        "{%0,%1,%2,%3}, {%4,%5,%6,%7}, {%8,%9}, {%0,%1,%2,%3};"
        : "+f"(d[0]), "+f"(d[1]), "+f"(d[2]), "+f"(d[3])
        : "r"(a[0]), "r"(a[1]), "r"(a[2]), "r"(a[3]), "r"(b[0]), "r"(b[1]));
}
__device__ __forceinline__ uint32_t cvt2(float lo, float hi) {
    __half2 h = __floats2half2_rn(lo, hi);
    return *reinterpret_cast<uint32_t*>(&h);
}
__device__ __forceinline__ uint32_t ldsb32(uint32_t addr) {
    uint32_t v;
    asm volatile("ld.shared.b32 %0, [%1];" : "=r"(v) : "r"(addr));
    return v;
}
__device__ __forceinline__ float dot4(float4 a, float4 b) {
    return a.x * b.x + a.y * b.y + a.z * b.z + a.w * b.w;
}

// ---------------- MLP layer (proven R14 structure) ------------------------
template <int IND, bool RELU, bool EMITB, bool BUILD>
__global__ __launch_bounds__(512)
void layer_kernel(const float* __restrict__ in, const float* __restrict__ W,
                  const float* __restrict__ bias, float* __restrict__ out,
                  const float* __restrict__ preference,
                  const float* __restrict__ pref_emb,
                  const float* __restrict__ chunk_emb) {
    constexpr int Q = IND / 4;
    __shared__ float4 in_s[8][Q];
    __shared__ float pe[64];

    int tid = threadIdx.x, lane = tid & 31, warp = tid >> 5;
    int cbase = blockIdx.y * 8;

    if (BUILD) {
        if (tid < 64)
            pe[tid] = preference[0] * pref_emb[tid] +
                      preference[1] * pref_emb[64 + tid];
        __syncthreads();
        for (int i = tid; i < 8 * Q; i += 512) {
            int c = i >> 5, q = i & 31;
            float4 v = make_float4(0.f, 0.f, 0.f, 0.f);
            if (cbase + c < NCHUNK) {
                if (q < 16)
                    v = reinterpret_cast<const float4*>(pe)[q];
                else
                    v = reinterpret_cast<const float4*>(chunk_emb)
                            [(cbase + c) * 16 + (q - 16)];
            }
            in_s[c][q] = v;
        }
    } else {
        for (int i = tid; i < 8 * Q; i += 512) {
            int c = i / Q, q = i % Q;
            float4 v = make_float4(0.f, 0.f, 0.f, 0.f);
            if (cbase + c < NCHUNK)
                v = reinterpret_cast<const float4*>(in)[(cbase + c) * Q + q];
            in_s[c][q] = v;
        }
    }
    __syncthreads();

    int j0 = blockIdx.x * 32 + warp * 2;
    int j1 = j0 + 1;
    const float4* W0 = reinterpret_cast<const float4*>(W) + (size_t)j0 * Q;
    const float4* W1r = reinterpret_cast<const float4*>(W) + (size_t)j1 * Q;

    float acc0[8], acc1[8];
#pragma unroll
    for (int c = 0; c < 8; c++) { acc0[c] = 0.f; acc1[c] = 0.f; }

#pragma unroll
    for (int ii = 0; ii < Q; ii += 32) {
        float4 w0 = W0[lane + ii];
        float4 w1 = W1r[lane + ii];
#pragma unroll
        for (int c = 0; c < 8; c++) {
            float4 x = in_s[c][lane + ii];
            acc0[c] += dot4(w0, x);
            acc1[c] += dot4(w1, x);
        }
    }

    float bj0 = 0.f, bj1 = 0.f;
    if (lane == 0) { bj0 = bias[j0]; bj1 = bias[j1]; }

    int aa0 = j0 & 15, aa1 = j1 & 15;
    int row0 = (j0 >> 4) * 8 + (aa0 >> 2) + 4 * ((aa0 >> 1) & 1);
    int row1 = (j1 >> 4) * 8 + (aa1 >> 2) + 4 * ((aa1 >> 1) & 1);
    int bs0 = aa0 & 1, bs1 = aa1 & 1;

#pragma unroll
    for (int c = 0; c < 8; c++) {
        float v0 = acc0[c], v1 = acc1[c];
#pragma unroll
        for (int off = 16; off; off >>= 1) {
            v0 += __shfl_down_sync(~0u, v0, off);
            v1 += __shfl_down_sync(~0u, v1, off);
        }
        if (lane == 0 && (cbase + c) < NCHUNK) {
            v0 += bj0; v1 += bj1;
            if (RELU) { v0 = fmaxf(v0, 0.f); v1 = fmaxf(v1, 0.f); }
            if (EMITB) {
                g_Bp[row0 * 224 + (cbase + c) * 2 + bs0] = __float2half_rn(v0);
                g_Bp[row1 * 224 + (cbase + c) * 2 + bs1] = __float2half_rn(v1);
            } else {
                out[(cbase + c) * HID + j0] = v0;
                out[(cbase + c) * HID + j1] = v1;
            }
        }
    }
}

// ---------------- big GEMM: out[n][m] = ws[m] . rep[n] -------------------
// N-split: CTA pair (2b, 2b+1) shares rows [b*256, +256); each holds an n56
// half-B image (72KB smem -> 2 CTAs/SM). A direct-LDG, 2-deep prefetch;
// pair's duplicate A reads hit L2.
__global__ __launch_bounds__(256, 2)
void big_kernel(const float* __restrict__ ws, float* __restrict__ out) {
    extern __shared__ char smem[];
    const uint32_t sb = smem_u32_of(smem);
    const int tid = threadIdx.x, lane = tid & 31, wid = tid >> 5;
    const int nhalf = blockIdx.x & 1;
    const long long brow = blockIdx.x >> 1;

    // load this CTA's half of the permuted B image (256 rows x 112 halves)
    {
        const float4* src = reinterpret_cast<const float4*>(g_Bp);
        for (int i = tid; i < 256 * 14; i += 256) {
            int r = i / 14, q = i - r * 14;
            *reinterpret_cast<float4*>(smem + r * BSROW + q * 16) =
                src[r * 28 + nhalf * 14 + q];
        }
    }
    __syncthreads();

    const int g = lane >> 2, q = lane & 3;
    const long long mwbase = brow * MT + wid * 32;

    const float4* ap[4];
#pragma unroll
    for (int j = 0; j < 4; j++) {
        long long r = mwbase + g + 8 * j;
        if (r >= NROWS) r = NROWS - 1;
        ap[j] = reinterpret_cast<const float4*>(ws) + r * (KD / 4) + q;
    }

    const uint32_t bbase = sb + (uint32_t)(lane & 3) * BSROW + (uint32_t)(lane >> 2) * 4;

    float acc[2][NTILES][4];
#pragma unroll
    for (int a = 0; a < 2; a++)
#pragma unroll
        for (int b = 0; b < NTILES; b++)
#pragma unroll
            for (int c = 0; c < 4; c++) acc[a][b][c] = 0.f;

    // 2-deep A prefetch (16 warps/SM provide the latency hiding)
    float4 pa[4][2];
#pragma unroll
    for (int j = 0; j < 4; j++) {
        pa[j][0] = ap[j][0];
        pa[j][1] = ap[j][4];
    }

#pragma unroll 4
    for (int t = 0; t < KSTEPS; t++) {
        float4 ca[4];
#pragma unroll
        for (int j = 0; j < 4; j++) {
            ca[j] = pa[j][t & 1];
            if (t + 2 < KSTEPS) pa[j][t & 1] = ap[j][(t + 2) * 4];
        }
        uint32_t ar[2][4];
        ar[0][0] = cvt2(ca[0].x, ca[0].y);
        ar[0][1] = cvt2(ca[1].x, ca[1].y);
        ar[0][2] = cvt2(ca[0].z, ca[0].w);
        ar[0][3] = cvt2(ca[1].z, ca[1].w);
        ar[1][0] = cvt2(ca[2].x, ca[2].y);
        ar[1][1] = cvt2(ca[3].x, ca[3].y);
        ar[1][2] = cvt2(ca[2].z, ca[2].w);
        ar[1][3] = cvt2(ca[3].z, ca[3].w);

        uint32_t browp = bbase + (uint32_t)t * (8 * BSROW);
#pragma unroll
        for (int nt = 0; nt < NTILES; nt++) {
            uint32_t bfr[2];
            bfr[0] = ldsb32(browp + nt * 32);
            bfr[1] = ldsb32(browp + 4 * BSROW + nt * 32);
            mma16816(acc[0][nt], ar[0], bfr);
            mma16816(acc[1][nt], ar[1], bfr);
        }
    }

    // ---- epilogue ----
#pragma unroll
    for (int tm = 0; tm < 2; tm++) {
        long long m0 = mwbase + tm * 16 + g;
        long long m1 = m0 + 8;
        int nb = 2 * q;
#pragma unroll
        for (int nt = 0; nt < NTILES; nt++) {
            int n0 = (nhalf * 7 + nt) * 8 + nb, n1 = n0 + 1;
            const float* c = acc[tm][nt];
            if (m0 < NROWS) {
                if (n0 < NCHUNK) out[(size_t)n0 * NROWS + m0] = c[0];
                if (n1 < NCHUNK) out[(size_t)n1 * NROWS + m0] = c[1];
            }
            if (m1 < NROWS) {
                if (n0 < NCHUNK) out[(size_t)n0 * NROWS + m1] = c[2];
                if (n1 < NCHUNK) out[(size_t)n1 * NROWS + m1] = c[3];
            }
        }
    }
}

// ---------------------------- launcher -----------------------------------
extern "C" void kernel_launch(void* const* d_in, const int* in_sizes, int n_in,
                              void* d_out, int out_size) {
    const float* preference = (const float*)d_in[0];
    const float* pref_emb   = (const float*)d_in[1];
    const float* chunk_emb  = (const float*)d_in[2];
    const float* W1         = (const float*)d_in[3];
    const float* b1         = (const float*)d_in[4];
    const float* W2         = (const float*)d_in[5];
    const float* b2         = (const float*)d_in[6];
    const float* W3         = (const float*)d_in[7];
    const float* b3         = (const float*)d_in[8];
    const float* ws         = (const float*)d_in[9];
    float* out = (float*)d_out;

    float *ph1, *ph2;
    cudaGetSymbolAddress((void**)&ph1, g_h1);
    cudaGetSymbolAddress((void**)&ph2, g_h2);

    static int attr_done = 0;
    if (!attr_done) {
        cudaFuncSetAttribute(big_kernel,
            cudaFuncAttributeMaxDynamicSharedMemorySize, BS_SMEM);
        attr_done = 1;
    }

    dim3 lgrid(HID / 32, (NCHUNK + 7) / 8);  // 16 x 14
    layer_kernel<IND1, true,  false, true ><<<lgrid, 512>>>(
        nullptr, W1, b1, ph1, preference, pref_emb, chunk_emb);
    layer_kernel<HID,  true,  false, false><<<lgrid, 512>>>(
        ph1, W2, b2, ph2, nullptr, nullptr, nullptr);
    layer_kernel<HID,  false, true,  false><<<lgrid, 512>>>(
        ph2, W3, b3, nullptr, nullptr, nullptr, nullptr);

    int nblocks = ((NROWS + MT - 1) / MT) * 2;   // 1720
    big_kernel<<<nblocks, 256, BS_SMEM>>>(ws, out);
}

// round 17
// speedup vs baseline: 1.2130x; 1.2130x over previous
#include <cuda_runtime.h>
#include <cuda_fp16.h>
#include <cstdint>

#define NCHUNK 105
#define HID    512
#define IND1   128
#define NROWS  220000
#define KD     512

// ---- big GEMM ----
#define MT     256            // rows per CTA (8 warps x m32)
#define KSTEPS 32             // k16 steps
// B image: per t (k16): 7 tile-pairs x 4 (8x8) matrices x 128B = 3584B
#define TBYTES 3584
#define BS_SMEM (KSTEPS * TBYTES)   // 114688

// ---------------- device scratch ----------------
__device__ float  g_h1 [NCHUNK * HID];
__device__ float  g_h2 [NCHUNK * HID];
__device__ __half g_Bp [BS_SMEM / 2];   // ldmatrix-ready fp16 B image

// ---------------- PTX helpers ----------------
__device__ __forceinline__ uint32_t smem_u32_of(const void* p) {
    uint32_t a;
    asm("{ .reg .u64 t; cvta.to.shared.u64 t, %1; cvt.u32.u64 %0, t; }" : "=r"(a) : "l"(p));
    return a;
}
__device__ __forceinline__ void mma16816(float* d, const uint32_t* a, const uint32_t* b) {
    asm volatile(
        "mma.sync.aligned.m16n8k16.row.col.f32.f16.f16.f32 "
        "{%0,%1,%2,%3}, {%4,%5,%6,%7}, {%8,%9}, {%0,%1,%2,%3};"
        : "+f"(d[0]), "+f"(d[1]), "+f"(d[2]), "+f"(d[3])
        : "r"(a[0]), "r"(a[1]), "r"(a[2]), "r"(a[3]), "r"(b[0]), "r"(b[1]));
}
__device__ __forceinline__ void ldsm4(uint32_t* r, uint32_t addr) {
    asm volatile("ldmatrix.sync.aligned.m8n8.x4.shared.b16 {%0,%1,%2,%3}, [%4];"
                 : "=r"(r[0]), "=r"(r[1]), "=r"(r[2]), "=r"(r[3]) : "r"(addr));
}
__device__ __forceinline__ uint32_t cvt2(float lo, float hi) {
    __half2 h = __floats2half2_rn(lo, hi);
    return *reinterpret_cast<uint32_t*>(&h);
}
__device__ __forceinline__ float dot4(float4 a, float4 b) {
    return a.x * b.x + a.y * b.y + a.z * b.z + a.w * b.w;
}

// B-image half index for value B[j][n] (j = hidden idx, n = chunk):
//   t = j>>4; aa = j&15; q=aa>>2; h=(aa>>1)&1; b=aa&1; col c = 2q+b
//   nt = n>>3; pair p = nt>>1; matrix m = (nt&1)*2 + h
//   idx = t*1792 + p*256 + m*64 + (n&7)*8 + c
__device__ __forceinline__ int bimg_idx(int j, int n) {
    int t = j >> 4, aa = j & 15;
    int c = 2 * (aa >> 2) + (aa & 1);
    int h = (aa >> 1) & 1;
    int nt = n >> 3;
    return t * 1792 + (nt >> 1) * 256 + ((nt & 1) * 2 + h) * 64 + (n & 7) * 8 + c;
}

// ---------------- MLP layer (proven R14 structure) ------------------------
template <int IND, bool RELU, bool EMITB, bool BUILD>
__global__ __launch_bounds__(512)
void layer_kernel(const float* __restrict__ in, const float* __restrict__ W,
                  const float* __restrict__ bias, float* __restrict__ out,
                  const float* __restrict__ preference,
                  const float* __restrict__ pref_emb,
                  const float* __restrict__ chunk_emb) {
    constexpr int Q = IND / 4;
    __shared__ float4 in_s[8][Q];
    __shared__ float pe[64];

    int tid = threadIdx.x, lane = tid & 31, warp = tid >> 5;
    int cbase = blockIdx.y * 8;

    if (BUILD) {
        if (tid < 64)
            pe[tid] = preference[0] * pref_emb[tid] +
                      preference[1] * pref_emb[64 + tid];
        __syncthreads();
        for (int i = tid; i < 8 * Q; i += 512) {
            int c = i >> 5, q = i & 31;
            float4 v = make_float4(0.f, 0.f, 0.f, 0.f);
            if (cbase + c < NCHUNK) {
                if (q < 16)
                    v = reinterpret_cast<const float4*>(pe)[q];
                else
                    v = reinterpret_cast<const float4*>(chunk_emb)
                            [(cbase + c) * 16 + (q - 16)];
            }
            in_s[c][q] = v;
        }
    } else {
        for (int i = tid; i < 8 * Q; i += 512) {
            int c = i / Q, q = i % Q;
            float4 v = make_float4(0.f, 0.f, 0.f, 0.f);
            if (cbase + c < NCHUNK)
                v = reinterpret_cast<const float4*>(in)[(cbase + c) * Q + q];
            in_s[c][q] = v;
        }
    }
    __syncthreads();

    int j0 = blockIdx.x * 32 + warp * 2;
    int j1 = j0 + 1;
    const float4* W0 = reinterpret_cast<const float4*>(W) + (size_t)j0 * Q;
    const float4* W1r = reinterpret_cast<const float4*>(W) + (size_t)j1 * Q;

    float acc0[8], acc1[8];
#pragma unroll
    for (int c = 0; c < 8; c++) { acc0[c] = 0.f; acc1[c] = 0.f; }

#pragma unroll
    for (int ii = 0; ii < Q; ii += 32) {
        float4 w0 = W0[lane + ii];
        float4 w1 = W1r[lane + ii];
#pragma unroll
        for (int c = 0; c < 8; c++) {
            float4 x = in_s[c][lane + ii];
            acc0[c] += dot4(w0, x);
            acc1[c] += dot4(w1, x);
        }
    }

    float bj0 = 0.f, bj1 = 0.f;
    if (lane == 0) { bj0 = bias[j0]; bj1 = bias[j1]; }

#pragma unroll
    for (int c = 0; c < 8; c++) {
        float v0 = acc0[c], v1 = acc1[c];
#pragma unroll
        for (int off = 16; off; off >>= 1) {
            v0 += __shfl_down_sync(~0u, v0, off);
            v1 += __shfl_down_sync(~0u, v1, off);
        }
        if (lane == 0 && (cbase + c) < NCHUNK) {
            v0 += bj0; v1 += bj1;
            if (RELU) { v0 = fmaxf(v0, 0.f); v1 = fmaxf(v1, 0.f); }
            if (EMITB) {
                int n = cbase + c;
                g_Bp[bimg_idx(j0, n)] = __float2half_rn(v0);
                g_Bp[bimg_idx(j1, n)] = __float2half_rn(v1);
            } else {
                out[(cbase + c) * HID + j0] = v0;
                out[(cbase + c) * HID + j1] = v1;
            }
        }
    }
}

// ---------------- zero pad rows of B image (n=105..111) ------------------
__global__ __launch_bounds__(256)
void zero_pad_kernel() {
    // pad n rows 105..111 -> zero those halves. Easiest: zero whole image
    // slots for n in [105,112): idx pattern has (n&7)*8 within matrix rows.
    // Simply zero all halves whose (idx mod 64)>>3 row corresponds to n>104:
    // iterate explicit (t,p,m,nr,c) with n = p*16 + (m>>1)*8 + nr.
    int i = blockIdx.x * 256 + threadIdx.x;
    // total pad elems: t(32) x j16 x n7 = 32*16*7 = 3584
    if (i >= 32 * 16 * 7) return;
    int t = i / (16 * 7);
    int r = i % (16 * 7);
    int aa = r / 7;          // 0..15 within-t j slot
    int n = 105 + (r % 7);   // 105..111
    int j = t * 16 + aa;
    g_Bp[bimg_idx(j, n)] = __float2half(0.f);
}

// ---------------- big GEMM: out[n][m] = ws[m] . rep[n] -------------------
// 256 thr (8 warps), warp tile m32 x n112, A direct-LDG (k-permuted,
// 4-deep prefetch), B image in SMEM read via ldmatrix.x4 (7 LDSM per k16).
__global__ __launch_bounds__(256, 1)
void big_kernel(const float* __restrict__ ws, float* __restrict__ out) {
    extern __shared__ char smem[];
    const uint32_t sb = smem_u32_of(smem);
    const int tid = threadIdx.x, lane = tid & 31, wid = tid >> 5;

    // load B image (contiguous copy)
    {
        const float4* src = reinterpret_cast<const float4*>(g_Bp);
        float4* dst = reinterpret_cast<float4*>(smem);
        for (int i = tid; i < BS_SMEM / 16; i += 256) dst[i] = src[i];
    }
    __syncthreads();

    const int g = lane >> 2, q = lane & 3;
    const long long mwbase = (long long)blockIdx.x * MT + wid * 32;

    const float4* ap[4];
#pragma unroll
    for (int j = 0; j < 4; j++) {
        long long r = mwbase + g + 8 * j;
        if (r >= NROWS) r = NROWS - 1;
        ap[j] = reinterpret_cast<const float4*>(ws) + r * (KD / 4) + q;
    }

    // ldmatrix lane address within a 512B tile-pair group
    const uint32_t lbase = sb + (uint32_t)((lane >> 3) * 128 + (lane & 7) * 16);

    float acc[2][14][4];
#pragma unroll
    for (int a = 0; a < 2; a++)
#pragma unroll
        for (int b = 0; b < 14; b++)
#pragma unroll
            for (int c = 0; c < 4; c++) acc[a][b][c] = 0.f;

    // 4-deep A prefetch (covers DRAM latency)
    float4 pa[4][4];
#pragma unroll
    for (int j = 0; j < 4; j++) {
#pragma unroll
        for (int d = 0; d < 4; d++) pa[j][d] = ap[j][d * 4];
    }

#pragma unroll 4
    for (int t = 0; t < KSTEPS; t++) {
        float4 ca[4];
#pragma unroll
        for (int j = 0; j < 4; j++) {
            ca[j] = pa[j][t & 3];
            if (t + 4 < KSTEPS) pa[j][t & 3] = ap[j][(t + 4) * 4];
        }
        uint32_t ar[2][4];
        ar[0][0] = cvt2(ca[0].x, ca[0].y);
        ar[0][1] = cvt2(ca[1].x, ca[1].y);
        ar[0][2] = cvt2(ca[0].z, ca[0].w);
        ar[0][3] = cvt2(ca[1].z, ca[1].w);
        ar[1][0] = cvt2(ca[2].x, ca[2].y);
        ar[1][1] = cvt2(ca[3].x, ca[3].y);
        ar[1][2] = cvt2(ca[2].z, ca[2].w);
        ar[1][3] = cvt2(ca[3].z, ca[3].w);

        uint32_t taddr = lbase + (uint32_t)t * TBYTES;
#pragma unroll
        for (int p = 0; p < 7; p++) {
            uint32_t r4[4];
            ldsm4(r4, taddr + p * 512);
            mma16816(acc[0][2 * p],     ar[0], r4 + 0);
            mma16816(acc[0][2 * p + 1], ar[0], r4 + 2);
            mma16816(acc[1][2 * p],     ar[1], r4 + 0);
            mma16816(acc[1][2 * p + 1], ar[1], r4 + 2);
        }
    }

    // ---- epilogue ----
#pragma unroll
    for (int tm = 0; tm < 2; tm++) {
        long long m0 = mwbase + tm * 16 + g;
        long long m1 = m0 + 8;
        int nb = 2 * q;
#pragma unroll
        for (int nt = 0; nt < 14; nt++) {
            int n0 = nt * 8 + nb, n1 = n0 + 1;
            const float* c = acc[tm][nt];
            if (m0 < NROWS) {
                if (n0 < NCHUNK) out[(size_t)n0 * NROWS + m0] = c[0];
                if (n1 < NCHUNK) out[(size_t)n1 * NROWS + m0] = c[1];
            }
            if (m1 < NROWS) {
                if (n0 < NCHUNK) out[(size_t)n0 * NROWS + m1] = c[2];
                if (n1 < NCHUNK) out[(size_t)n1 * NROWS + m1] = c[3];
            }
        }
    }
}

// ---------------------------- launcher -----------------------------------
extern "C" void kernel_launch(void* const* d_in, const int* in_sizes, int n_in,
                              void* d_out, int out_size) {
    const float* preference = (const float*)d_in[0];
    const float* pref_emb   = (const float*)d_in[1];
    const float* chunk_emb  = (const float*)d_in[2];
    const float* W1         = (const float*)d_in[3];
    const float* b1         = (const float*)d_in[4];
    const float* W2         = (const float*)d_in[5];
    const float* b2         = (const float*)d_in[6];
    const float* W3         = (const float*)d_in[7];
    const float* b3         = (const float*)d_in[8];
    const float* ws         = (const float*)d_in[9];
    float* out = (float*)d_out;

    float *ph1, *ph2;
    cudaGetSymbolAddress((void**)&ph1, g_h1);
    cudaGetSymbolAddress((void**)&ph2, g_h2);

    static int attr_done = 0;
    if (!attr_done) {
        cudaFuncSetAttribute(big_kernel,
            cudaFuncAttributeMaxDynamicSharedMemorySize, BS_SMEM);
        attr_done = 1;
    }

    zero_pad_kernel<<<(32 * 16 * 7 + 255) / 256, 256>>>();

    dim3 lgrid(HID / 32, (NCHUNK + 7) / 8);  // 16 x 14
    layer_kernel<IND1, true,  false, true ><<<lgrid, 512>>>(
        nullptr, W1, b1, ph1, preference, pref_emb, chunk_emb);
    layer_kernel<HID,  true,  false, false><<<lgrid, 512>>>(
        ph1, W2, b2, ph2, nullptr, nullptr, nullptr);
    layer_kernel<HID,  false, true,  false><<<lgrid, 512>>>(
        ph2, W3, b3, nullptr, nullptr, nullptr, nullptr);

    int nblocks = (NROWS + MT - 1) / MT;   // 860
    big_kernel<<<nblocks, 256, BS_SMEM>>>(ws, out);
}